// round 3
// baseline (speedup 1.0000x reference)
#include <cuda_runtime.h>

#define TTOK 3136
#define DM 512

// Scratch (device globals — no allocation allowed)
__device__ float g_q[TTOK * DM];
__device__ float g_k[TTOK * DM];
__device__ float g_v[TTOK * DM];
__device__ float g_ao[TTOK * DM];

// ---------------------------------------------------------------------------
// GEMM: out[M=3136, N=512] = (A1 (+A2)) @ W[512,512] + bias
// Tiles: BM=64, BN=64, BK=16; 256 threads; 4x4 microtile per thread.
// ---------------------------------------------------------------------------
__device__ __forceinline__ void gemm_body(
    const float* __restrict__ A1, const float* __restrict__ A2,
    const float* __restrict__ W, const float* __restrict__ bias,
    float* __restrict__ out, int m0, int n0)
{
    __shared__ float As[16][68];   // transposed A tile: As[k][m]
    __shared__ float Bs[16][68];

    const int tid = threadIdx.x;
    const int tx = tid & 15, ty = tid >> 4;

    const int ar = tid >> 2,  ac4 = tid & 3;    // A tile: 64 rows x 4 float4
    const int br = tid >> 4,  bc4 = tid & 15;   // B tile: 16 rows x 16 float4

    float acc[4][4];
    #pragma unroll
    for (int i = 0; i < 4; i++)
        #pragma unroll
        for (int j = 0; j < 4; j++) acc[i][j] = 0.f;

    for (int k0 = 0; k0 < DM; k0 += 16) {
        float4 a = *(const float4*)(A1 + (size_t)(m0 + ar) * DM + k0 + ac4 * 4);
        if (A2) {
            float4 p2 = *(const float4*)(A2 + (size_t)(m0 + ar) * DM + k0 + ac4 * 4);
            a.x += p2.x; a.y += p2.y; a.z += p2.z; a.w += p2.w;
        }
        As[ac4 * 4 + 0][ar] = a.x;
        As[ac4 * 4 + 1][ar] = a.y;
        As[ac4 * 4 + 2][ar] = a.z;
        As[ac4 * 4 + 3][ar] = a.w;

        float4 b = *(const float4*)(W + (size_t)(k0 + br) * DM + n0 + bc4 * 4);
        *(float4*)&Bs[br][bc4 * 4] = b;

        __syncthreads();
        #pragma unroll
        for (int kk = 0; kk < 16; kk++) {
            float4 av = *(float4*)&As[kk][ty * 4];
            float4 bv = *(float4*)&Bs[kk][tx * 4];
            float aa[4] = {av.x, av.y, av.z, av.w};
            float bb[4] = {bv.x, bv.y, bv.z, bv.w};
            #pragma unroll
            for (int i = 0; i < 4; i++)
                #pragma unroll
                for (int j = 0; j < 4; j++)
                    acc[i][j] += aa[i] * bb[j];
        }
        __syncthreads();
    }

    #pragma unroll
    for (int i = 0; i < 4; i++) {
        int m = m0 + ty * 4 + i;
        #pragma unroll
        for (int j = 0; j < 4; j++) {
            int n = n0 + tx * 4 + j;
            out[(size_t)m * DM + n] = acc[i][j] + bias[n];
        }
    }
}

__global__ __launch_bounds__(256) void gemm512_kernel(
    const float* __restrict__ A1, const float* __restrict__ A2,
    const float* __restrict__ W, const float* __restrict__ bias,
    float* __restrict__ out)
{
    gemm_body(A1, A2, W, bias, out, blockIdx.y * 64, blockIdx.x * 64);
}

// Fused Q/K/V projections: blockIdx.z selects which projection.
__global__ __launch_bounds__(256) void gemm_qkv_kernel(
    const float* __restrict__ xq, const float* __restrict__ xk,
    const float* __restrict__ pos,
    const float* __restrict__ Wq, const float* __restrict__ bq,
    const float* __restrict__ Wk, const float* __restrict__ bk,
    const float* __restrict__ Wv, const float* __restrict__ bv,
    float* __restrict__ oq, float* __restrict__ ok, float* __restrict__ ov)
{
    const float *A1, *A2, *W, *bias; float* out;
    if (blockIdx.z == 0)      { A1 = xq; A2 = pos;     W = Wq; bias = bq; out = oq; }
    else if (blockIdx.z == 1) { A1 = xk; A2 = pos;     W = Wk; bias = bk; out = ok; }
    else                      { A1 = xk; A2 = nullptr; W = Wv; bias = bv; out = ov; }
    gemm_body(A1, A2, W, bias, out, blockIdx.y * 64, blockIdx.x * 64);
}

// ---------------------------------------------------------------------------
// Block-diagonal flash attention, register-tiled GEMM formulation.
// Grid: (T/64, H). Block: 256 threads = 16x16 grid of 4x4 microtiles.
// Per KV tile: S = Q @ K^T (64x64), online softmax, O += P @ V (64x64).
// Smem: Qt[d][m], Kt[d][n], Vs[k][d], Ps[k][m]  (all stride 68).
// ---------------------------------------------------------------------------
#define AST 68
#define ATTN_SMEM_FLOATS (4 * 64 * AST)

__global__ __launch_bounds__(256, 3) void attn_kernel(
    const float* __restrict__ gq, const float* __restrict__ gk,
    const float* __restrict__ gv, const int* __restrict__ channels,
    float* __restrict__ gout)
{
    extern __shared__ float sm[];
    float* Qt = sm;                 // [64 d][68]  (Q transposed)
    float* Kt = Qt + 64 * AST;      // [64 d][68]  (K transposed)
    float* Vs = Kt + 64 * AST;      // [64 k][68]  (V natural)
    float* Ps = Vs + 64 * AST;      // [64 k][68]  (P transposed: Ps[k][m])

    const int h   = blockIdx.y;
    const int q0  = blockIdx.x * 64;
    const int tid = threadIdx.x;
    const int tx  = tid & 15, ty = tid >> 4;

    // Segment boundaries (all multiples of 4, so 4-row microtiles never straddle)
    int bnd1 = channels[0] * 196;
    int bnd2 = bnd1 + channels[1] * 196;
    int bnd3 = bnd2 + channels[2] * 196;
    int bnd4 = bnd3 + channels[3] * 196;

    // Segment bounds for this thread's 4 rows (q0 + ty*4 .. +3, same segment)
    int my_t = q0 + ty * 4;
    int my_s, my_e;
    if      (my_t < bnd1) { my_s = 0;    my_e = bnd1; }
    else if (my_t < bnd2) { my_s = bnd1; my_e = bnd2; }
    else if (my_t < bnd3) { my_s = bnd2; my_e = bnd3; }
    else                  { my_s = bnd3; my_e = bnd4; }

    // Block-wide kv range (covers segments of first and last row)
    int t0 = q0, t1 = q0 + 63;
    int blk_s, blk_e;
    if      (t0 < bnd1) blk_s = 0;
    else if (t0 < bnd2) blk_s = bnd1;
    else if (t0 < bnd3) blk_s = bnd2;
    else                blk_s = bnd3;
    if      (t1 < bnd1) blk_e = bnd1;
    else if (t1 < bnd2) blk_e = bnd2;
    else if (t1 < bnd3) blk_e = bnd3;
    else                blk_e = bnd4;

    // Load Q tile transposed: Qt[c][r] = Q[q0+r][h*64+c]
    // 64 rows x 16 float4-chunks = 1024 float4s over 256 threads (4 each).
    for (int i = tid; i < 64 * 16; i += 256) {
        int r = i >> 4, c4 = i & 15;
        float4 qv = *(const float4*)(gq + (size_t)(q0 + r) * DM + h * 64 + c4 * 4);
        Qt[(c4 * 4 + 0) * AST + r] = qv.x;
        Qt[(c4 * 4 + 1) * AST + r] = qv.y;
        Qt[(c4 * 4 + 2) * AST + r] = qv.z;
        Qt[(c4 * 4 + 3) * AST + r] = qv.w;
    }

    float o[4][4];
    #pragma unroll
    for (int i = 0; i < 4; i++)
        #pragma unroll
        for (int j = 0; j < 4; j++) o[i][j] = 0.f;
    float m_i[4], l_i[4];
    #pragma unroll
    for (int i = 0; i < 4; i++) { m_i[i] = -1e30f; l_i[i] = 0.f; }

    for (int kv = blk_s; kv < blk_e; kv += 64) {
        __syncthreads();
        // Load K (transposed) and V (natural) tiles
        for (int i = tid; i < 64 * 16; i += 256) {
            int r = i >> 4, c4 = i & 15;
            int kr = kv + r;
            float4 kx = make_float4(0.f, 0.f, 0.f, 0.f);
            float4 vx = make_float4(0.f, 0.f, 0.f, 0.f);
            if (kr < TTOK) {
                kx = *(const float4*)(gk + (size_t)kr * DM + h * 64 + c4 * 4);
                vx = *(const float4*)(gv + (size_t)kr * DM + h * 64 + c4 * 4);
            }
            Kt[(c4 * 4 + 0) * AST + r] = kx.x;
            Kt[(c4 * 4 + 1) * AST + r] = kx.y;
            Kt[(c4 * 4 + 2) * AST + r] = kx.z;
            Kt[(c4 * 4 + 3) * AST + r] = kx.w;
            *(float4*)&Vs[r * AST + c4 * 4] = vx;
        }
        __syncthreads();

        // S microtile: s[i][j] = sum_d Q[row i][d] * K[col j][d]
        float s_[4][4];
        #pragma unroll
        for (int i = 0; i < 4; i++)
            #pragma unroll
            for (int j = 0; j < 4; j++) s_[i][j] = 0.f;
        #pragma unroll 16
        for (int kk = 0; kk < 64; kk++) {
            float4 av = *(float4*)&Qt[kk * AST + ty * 4];
            float4 bv = *(float4*)&Kt[kk * AST + tx * 4];
            float aa[4] = {av.x, av.y, av.z, av.w};
            float bb[4] = {bv.x, bv.y, bv.z, bv.w};
            #pragma unroll
            for (int i = 0; i < 4; i++)
                #pragma unroll
                for (int j = 0; j < 4; j++)
                    s_[i][j] += aa[i] * bb[j];
        }

        // Mask + scale; per-row max over this thread's 4 cols
        bool valid[4];
        #pragma unroll
        for (int j = 0; j < 4; j++) {
            int kg = kv + tx * 4 + j;
            valid[j] = (kg >= my_s && kg < my_e);
        }
        float mloc[4];
        #pragma unroll
        for (int i = 0; i < 4; i++) {
            mloc[i] = -1e30f;
            #pragma unroll
            for (int j = 0; j < 4; j++) {
                s_[i][j] = valid[j] ? s_[i][j] * 0.125f : -1e30f;
                mloc[i] = fmaxf(mloc[i], s_[i][j]);
            }
        }
        // Reduce across the 16 tx-lanes (lane = (ty&1)*16 + tx; off<16 stays in group)
        #pragma unroll
        for (int off = 1; off < 16; off <<= 1) {
            #pragma unroll
            for (int i = 0; i < 4; i++)
                mloc[i] = fmaxf(mloc[i], __shfl_xor_sync(0xffffffffu, mloc[i], off));
        }

        float alpha[4], m_new[4];
        #pragma unroll
        for (int i = 0; i < 4; i++) {
            m_new[i] = fmaxf(m_i[i], mloc[i]);
            alpha[i] = __expf(m_i[i] - m_new[i]);
            m_i[i] = m_new[i];
        }

        // p = exp(s - m_new) (guarded!), write transposed Ps[k][m], row-sum
        float lloc[4];
        #pragma unroll
        for (int i = 0; i < 4; i++) lloc[i] = 0.f;
        #pragma unroll
        for (int i = 0; i < 4; i++) {
            #pragma unroll
            for (int j = 0; j < 4; j++) {
                float p = valid[j] ? __expf(s_[i][j] - m_new[i]) : 0.f;
                Ps[(tx * 4 + j) * AST + ty * 4 + i] = p;
                lloc[i] += p;
            }
        }
        #pragma unroll
        for (int off = 1; off < 16; off <<= 1) {
            #pragma unroll
            for (int i = 0; i < 4; i++)
                lloc[i] += __shfl_xor_sync(0xffffffffu, lloc[i], off);
        }
        #pragma unroll
        for (int i = 0; i < 4; i++) {
            l_i[i] = l_i[i] * alpha[i] + lloc[i];
            #pragma unroll
            for (int j = 0; j < 4; j++) o[i][j] *= alpha[i];
        }

        __syncthreads();   // Ps visible to all

        // O += P @ V : o[i][j] += sum_k Ps[k][row i] * Vs[k][dim j]
        #pragma unroll 16
        for (int kk = 0; kk < 64; kk++) {
            float4 av = *(float4*)&Ps[kk * AST + ty * 4];
            float4 bv = *(float4*)&Vs[kk * AST + tx * 4];
            float aa[4] = {av.x, av.y, av.z, av.w};
            float bb[4] = {bv.x, bv.y, bv.z, bv.w};
            #pragma unroll
            for (int i = 0; i < 4; i++)
                #pragma unroll
                for (int j = 0; j < 4; j++)
                    o[i][j] += aa[i] * bb[j];
        }
    }

    #pragma unroll
    for (int i = 0; i < 4; i++) {
        float inv = 1.f / l_i[i];
        #pragma unroll
        for (int j = 0; j < 4; j++)
            gout[(size_t)(q0 + ty * 4 + i) * DM + h * 64 + tx * 4 + j] = o[i][j] * inv;
    }
}

// ---------------------------------------------------------------------------
// Launch
// ---------------------------------------------------------------------------
extern "C" void kernel_launch(void* const* d_in, const int* in_sizes, int n_in,
                              void* d_out, int out_size)
{
    const float* xq  = (const float*)d_in[0];
    const float* xk  = (const float*)d_in[1];
    const float* pos = (const float*)d_in[2];
    const int*   ch  = (const int*)  d_in[3];
    const float* Wq  = (const float*)d_in[4];
    const float* bq  = (const float*)d_in[5];
    const float* Wk  = (const float*)d_in[6];
    const float* bk  = (const float*)d_in[7];
    const float* Wv  = (const float*)d_in[8];
    const float* bv  = (const float*)d_in[9];
    const float* Wo  = (const float*)d_in[10];
    const float* bo  = (const float*)d_in[11];
    float* out = (float*)d_out;

    float *q, *k, *v, *ao;
    cudaGetSymbolAddress((void**)&q,  g_q);
    cudaGetSymbolAddress((void**)&k,  g_k);
    cudaGetSymbolAddress((void**)&v,  g_v);
    cudaGetSymbolAddress((void**)&ao, g_ao);

    const size_t attn_smem = ATTN_SMEM_FLOATS * sizeof(float);
    cudaFuncSetAttribute(attn_kernel, cudaFuncAttributeMaxDynamicSharedMemorySize,
                         (int)attn_smem);

    dim3 gqkv(DM / 64, TTOK / 64, 3);   // (8, 49, 3)
    gemm_qkv_kernel<<<gqkv, 256>>>(xq, xk, pos, Wq, bq, Wk, bk, Wv, bv, q, k, v);

    attn_kernel<<<dim3(TTOK / 64, 8), 256, attn_smem>>>(q, k, v, ch, ao);

    dim3 gg(DM / 64, TTOK / 64);        // (8, 49)
    gemm512_kernel<<<gg, 256>>>(ao, nullptr, Wo, bo, out);
}

// round 4
// speedup vs baseline: 2.1742x; 2.1742x over previous
#include <cuda_runtime.h>

#define TTOK 3136
#define DM 512

// Scratch (device globals — no allocation allowed)
__device__ float g_q[TTOK * DM];
__device__ float g_k[TTOK * DM];
__device__ float g_v[TTOK * DM];
__device__ float g_ao[TTOK * DM];

// ---------------------------------------------------------------------------
// Packed f32x2 helpers (FFMA2 path on sm_103a)
// ---------------------------------------------------------------------------
typedef unsigned long long u64t;

__device__ __forceinline__ u64t dup2(float x) {
    u64t r; asm("mov.b64 %0,{%1,%1};" : "=l"(r) : "f"(x)); return r;
}
__device__ __forceinline__ u64t ffma2(u64t a, u64t b, u64t c) {
    u64t d; asm("fma.rn.f32x2 %0,%1,%2,%3;" : "=l"(d) : "l"(a), "l"(b), "l"(c));
    return d;
}
__device__ __forceinline__ u64t mul2(u64t a, u64t b) {
    u64t d; asm("mul.rn.f32x2 %0,%1,%2;" : "=l"(d) : "l"(a), "l"(b));
    return d;
}
__device__ __forceinline__ float2 upk(u64t v) {
    float2 f; asm("mov.b64 {%0,%1},%2;" : "=f"(f.x), "=f"(f.y) : "l"(v));
    return f;
}

// ---------------------------------------------------------------------------
// GEMM: out[3136, 512] = (A1 (+A2)) @ W[512,512] + bias
// BM=64, BN=128, BK=16; 128 threads; 8x8 microtile, f32x2 packed FMA.
// ---------------------------------------------------------------------------
__device__ __forceinline__ void gemm_body(
    const float* __restrict__ A1, const float* __restrict__ A2,
    const float* __restrict__ W, const float* __restrict__ bias,
    float* __restrict__ out, int m0, int n0)
{
    __shared__ float As[16][68];    // transposed A tile: As[k][m] (64 wide)
    __shared__ float Bs[16][132];   // Bs[k][n] (128 wide)

    const int tid = threadIdx.x;
    const int tx = tid & 15;        // col group: n0 + tx*8
    const int ty = tid >> 4;        // row group: m0 + ty*8 (0..7)

    u64t acc[8][4];
    #pragma unroll
    for (int i = 0; i < 8; i++)
        #pragma unroll
        for (int jp = 0; jp < 4; jp++) acc[i][jp] = 0ULL;

    for (int k0 = 0; k0 < DM; k0 += 16) {
        // A tile: 64 rows x 16 cols = 256 float4s; 2 per thread. Transposed store.
        #pragma unroll
        for (int it = 0; it < 2; it++) {
            int i = tid + it * 128;
            int r = i >> 2, c4 = i & 3;
            float4 a = *(const float4*)(A1 + (size_t)(m0 + r) * DM + k0 + c4 * 4);
            if (A2) {
                float4 p = *(const float4*)(A2 + (size_t)(m0 + r) * DM + k0 + c4 * 4);
                a.x += p.x; a.y += p.y; a.z += p.z; a.w += p.w;
            }
            As[c4 * 4 + 0][r] = a.x;
            As[c4 * 4 + 1][r] = a.y;
            As[c4 * 4 + 2][r] = a.z;
            As[c4 * 4 + 3][r] = a.w;
        }
        // B tile: 16 rows x 128 cols = 512 float4s; 4 per thread.
        #pragma unroll
        for (int it = 0; it < 4; it++) {
            int i = tid + it * 128;
            int r = i >> 5, c4 = i & 31;
            *(float4*)&Bs[r][c4 * 4] =
                *(const float4*)(W + (size_t)(k0 + r) * DM + n0 + c4 * 4);
        }
        __syncthreads();

        #pragma unroll
        for (int kk = 0; kk < 16; kk++) {
            float4 a0 = *(float4*)&As[kk][ty * 8];
            float4 a1 = *(float4*)&As[kk][ty * 8 + 4];
            ulonglong2 b0 = *(ulonglong2*)&Bs[kk][tx * 8];
            ulonglong2 b1 = *(ulonglong2*)&Bs[kk][tx * 8 + 4];
            float av[8] = {a0.x, a0.y, a0.z, a0.w, a1.x, a1.y, a1.z, a1.w};
            u64t bp[4] = {b0.x, b0.y, b1.x, b1.y};
            #pragma unroll
            for (int i = 0; i < 8; i++) {
                u64t ad = dup2(av[i]);
                #pragma unroll
                for (int jp = 0; jp < 4; jp++)
                    acc[i][jp] = ffma2(ad, bp[jp], acc[i][jp]);
            }
        }
        __syncthreads();
    }

    float4 bA = *(const float4*)&bias[n0 + tx * 8];
    float4 bB = *(const float4*)&bias[n0 + tx * 8 + 4];
    #pragma unroll
    for (int i = 0; i < 8; i++) {
        int m = m0 + ty * 8 + i;
        float2 r0 = upk(acc[i][0]), r1 = upk(acc[i][1]);
        float2 r2 = upk(acc[i][2]), r3 = upk(acc[i][3]);
        float4 o0 = make_float4(r0.x + bA.x, r0.y + bA.y, r1.x + bA.z, r1.y + bA.w);
        float4 o1 = make_float4(r2.x + bB.x, r2.y + bB.y, r3.x + bB.z, r3.y + bB.w);
        *(float4*)&out[(size_t)m * DM + n0 + tx * 8]     = o0;
        *(float4*)&out[(size_t)m * DM + n0 + tx * 8 + 4] = o1;
    }
}

__global__ __launch_bounds__(128, 4) void gemm512_kernel(
    const float* __restrict__ A1, const float* __restrict__ A2,
    const float* __restrict__ W, const float* __restrict__ bias,
    float* __restrict__ out)
{
    gemm_body(A1, A2, W, bias, out, blockIdx.y * 64, blockIdx.x * 128);
}

__global__ __launch_bounds__(128, 4) void gemm_qkv_kernel(
    const float* __restrict__ xq, const float* __restrict__ xk,
    const float* __restrict__ pos,
    const float* __restrict__ Wq, const float* __restrict__ bq,
    const float* __restrict__ Wk, const float* __restrict__ bk,
    const float* __restrict__ Wv, const float* __restrict__ bv,
    float* __restrict__ oq, float* __restrict__ ok, float* __restrict__ ov)
{
    const float *A1, *A2, *W, *bias; float* out;
    if (blockIdx.z == 0)      { A1 = xq; A2 = pos;     W = Wq; bias = bq; out = oq; }
    else if (blockIdx.z == 1) { A1 = xk; A2 = pos;     W = Wk; bias = bk; out = ok; }
    else                      { A1 = xk; A2 = nullptr; W = Wv; bias = bv; out = ov; }
    gemm_body(A1, A2, W, bias, out, blockIdx.y * 64, blockIdx.x * 128);
}

// ---------------------------------------------------------------------------
// Block-diagonal flash attention, segment-aligned q-blocks, f32x2 FMA.
// Grid: (52, H). 52 = sum over segments of ceil(len/64) for channels [2,4,6,4].
// Block: 128 threads = 16(tx: 4 kv-cols / 4 out-dims) x 8(ty: 8 q-rows).
// Per KV tile: S = Q K^T (64x64), online softmax, O += P V.
// ---------------------------------------------------------------------------
#define KST 68
#define ATTN_SMEM_FLOATS (4 * 64 * KST)

__global__ __launch_bounds__(128, 3) void attn_kernel(
    const float* __restrict__ gq, const float* __restrict__ gk,
    const float* __restrict__ gv, const int* __restrict__ channels,
    float* __restrict__ gout)
{
    extern __shared__ float sm[];
    float* Qt = sm;                 // [64 d][68]  Q transposed [d][m]
    float* Kt = Qt + 64 * KST;      // [64 d][68]  K transposed [d][kv]
    float* Vs = Kt + 64 * KST;      // [64 k][68]  V natural [k][d]
    float* Pt = Vs + 64 * KST;      // [64 k][68]  P transposed [k][m]

    const int h   = blockIdx.y;
    const int tid = threadIdx.x;
    const int tx  = tid & 15;       // kv cols tx*4 / out dims tx*4
    const int ty  = tid >> 4;       // q rows ty*8 (0..7)

    // Map blockIdx.x -> (q0, segment) so no block straddles a segment.
    int b = blockIdx.x, seg_s = 0, seg_e = 0, q0 = 0;
    #pragma unroll
    for (int i = 0; i < 4; i++) {
        if (b >= 0) {
            int len = channels[i] * 196;
            int nb = (len + 63) >> 6;
            if (b < nb) { q0 = seg_s + b * 64; seg_e = seg_s + len; b = -1; }
            else        { b -= nb; seg_s += len; }
        }
    }

    // Load Q tile transposed (rows beyond segment end -> zeros)
    #pragma unroll
    for (int it = 0; it < 8; it++) {
        int i = tid + it * 128;
        int r = i >> 4, c4 = i & 15;
        int qr = q0 + r;
        float4 qv = make_float4(0.f, 0.f, 0.f, 0.f);
        if (qr < seg_e)
            qv = *(const float4*)(gq + (size_t)qr * DM + h * 64 + c4 * 4);
        Qt[(c4 * 4 + 0) * KST + r] = qv.x;
        Qt[(c4 * 4 + 1) * KST + r] = qv.y;
        Qt[(c4 * 4 + 2) * KST + r] = qv.z;
        Qt[(c4 * 4 + 3) * KST + r] = qv.w;
    }

    u64t o2[8][2];
    float m_i[8], l_i[8];
    #pragma unroll
    for (int i = 0; i < 8; i++) {
        o2[i][0] = 0ULL; o2[i][1] = 0ULL;
        m_i[i] = -1e30f; l_i[i] = 0.f;
    }

    for (int kv0 = seg_s; kv0 < seg_e; kv0 += 64) {
        __syncthreads();
        // K (transposed) + V (natural), rows beyond segment -> zeros
        #pragma unroll
        for (int it = 0; it < 8; it++) {
            int i = tid + it * 128;
            int r = i >> 4, c4 = i & 15;
            int kr = kv0 + r;
            float4 kx = make_float4(0.f, 0.f, 0.f, 0.f);
            float4 vx = make_float4(0.f, 0.f, 0.f, 0.f);
            if (kr < seg_e) {
                kx = *(const float4*)(gk + (size_t)kr * DM + h * 64 + c4 * 4);
                vx = *(const float4*)(gv + (size_t)kr * DM + h * 64 + c4 * 4);
            }
            Kt[(c4 * 4 + 0) * KST + r] = kx.x;
            Kt[(c4 * 4 + 1) * KST + r] = kx.y;
            Kt[(c4 * 4 + 2) * KST + r] = kx.z;
            Kt[(c4 * 4 + 3) * KST + r] = kx.w;
            *(float4*)&Vs[r * KST + c4 * 4] = vx;
        }
        __syncthreads();

        // S = Q K^T : 8 rows x 4 cols per thread (2 f32x2 pairs)
        u64t s2[8][2];
        #pragma unroll
        for (int i = 0; i < 8; i++) { s2[i][0] = 0ULL; s2[i][1] = 0ULL; }
        #pragma unroll 8
        for (int kk = 0; kk < 64; kk++) {
            float4 a0 = *(float4*)&Qt[kk * KST + ty * 8];
            float4 a1 = *(float4*)&Qt[kk * KST + ty * 8 + 4];
            ulonglong2 bq = *(ulonglong2*)&Kt[kk * KST + tx * 4];
            float av[8] = {a0.x, a0.y, a0.z, a0.w, a1.x, a1.y, a1.z, a1.w};
            #pragma unroll
            for (int i = 0; i < 8; i++) {
                u64t ad = dup2(av[i]);
                s2[i][0] = ffma2(ad, bq.x, s2[i][0]);
                s2[i][1] = ffma2(ad, bq.y, s2[i][1]);
            }
        }

        // Unpack, mask, scale
        bool valid[4];
        #pragma unroll
        for (int j = 0; j < 4; j++)
            valid[j] = (kv0 + tx * 4 + j) < seg_e;

        float s[8][4], mloc[8];
        #pragma unroll
        for (int i = 0; i < 8; i++) {
            float2 f0 = upk(s2[i][0]), f1 = upk(s2[i][1]);
            s[i][0] = f0.x; s[i][1] = f0.y; s[i][2] = f1.x; s[i][3] = f1.y;
            mloc[i] = -1e30f;
            #pragma unroll
            for (int j = 0; j < 4; j++) {
                s[i][j] = valid[j] ? s[i][j] * 0.125f : -1e30f;
                mloc[i] = fmaxf(mloc[i], s[i][j]);
            }
        }
        // Row-max across 16 tx-lanes (lane = (ty&1)*16 + tx; xor<16 stays in group)
        #pragma unroll
        for (int off = 1; off < 16; off <<= 1)
            #pragma unroll
            for (int i = 0; i < 8; i++)
                mloc[i] = fmaxf(mloc[i], __shfl_xor_sync(0xffffffffu, mloc[i], off));

        float alpha[8];
        #pragma unroll
        for (int i = 0; i < 8; i++) {
            float m_new = fmaxf(m_i[i], mloc[i]);
            alpha[i] = __expf(m_i[i] - m_new);
            m_i[i] = m_new;
        }

        float p_[8][4], lloc[8];
        #pragma unroll
        for (int i = 0; i < 8; i++) {
            lloc[i] = 0.f;
            #pragma unroll
            for (int j = 0; j < 4; j++) {
                float p = valid[j] ? __expf(s[i][j] - m_i[i]) : 0.f;
                p_[i][j] = p;
                lloc[i] += p;
            }
        }
        #pragma unroll
        for (int off = 1; off < 16; off <<= 1)
            #pragma unroll
            for (int i = 0; i < 8; i++)
                lloc[i] += __shfl_xor_sync(0xffffffffu, lloc[i], off);

        #pragma unroll
        for (int i = 0; i < 8; i++) {
            l_i[i] = l_i[i] * alpha[i] + lloc[i];
            u64t ad = dup2(alpha[i]);
            o2[i][0] = mul2(o2[i][0], ad);
            o2[i][1] = mul2(o2[i][1], ad);
        }

        // Store P transposed: for each k (=tx*4+j), 8 consecutive m -> 2 STS.128
        #pragma unroll
        for (int j = 0; j < 4; j++) {
            *(float4*)&Pt[(tx * 4 + j) * KST + ty * 8] =
                make_float4(p_[0][j], p_[1][j], p_[2][j], p_[3][j]);
            *(float4*)&Pt[(tx * 4 + j) * KST + ty * 8 + 4] =
                make_float4(p_[4][j], p_[5][j], p_[6][j], p_[7][j]);
        }
        __syncthreads();

        // O += P V : 8 rows x 4 dims per thread
        #pragma unroll 8
        for (int kk = 0; kk < 64; kk++) {
            float4 a0 = *(float4*)&Pt[kk * KST + ty * 8];
            float4 a1 = *(float4*)&Pt[kk * KST + ty * 8 + 4];
            ulonglong2 bv = *(ulonglong2*)&Vs[kk * KST + tx * 4];
            float av[8] = {a0.x, a0.y, a0.z, a0.w, a1.x, a1.y, a1.z, a1.w};
            #pragma unroll
            for (int i = 0; i < 8; i++) {
                u64t ad = dup2(av[i]);
                o2[i][0] = ffma2(ad, bv.x, o2[i][0]);
                o2[i][1] = ffma2(ad, bv.y, o2[i][1]);
            }
        }
    }

    #pragma unroll
    for (int i = 0; i < 8; i++) {
        int row = q0 + ty * 8 + i;
        if (row < seg_e) {
            float inv = 1.f / l_i[i];
            float2 f0 = upk(o2[i][0]), f1 = upk(o2[i][1]);
            float4 ov = make_float4(f0.x * inv, f0.y * inv, f1.x * inv, f1.y * inv);
            *(float4*)&gout[(size_t)row * DM + h * 64 + tx * 4] = ov;
        }
    }
}

// ---------------------------------------------------------------------------
// Launch
// ---------------------------------------------------------------------------
extern "C" void kernel_launch(void* const* d_in, const int* in_sizes, int n_in,
                              void* d_out, int out_size)
{
    const float* xq  = (const float*)d_in[0];
    const float* xk  = (const float*)d_in[1];
    const float* pos = (const float*)d_in[2];
    const int*   ch  = (const int*)  d_in[3];
    const float* Wq  = (const float*)d_in[4];
    const float* bq  = (const float*)d_in[5];
    const float* Wk  = (const float*)d_in[6];
    const float* bk  = (const float*)d_in[7];
    const float* Wv  = (const float*)d_in[8];
    const float* bv  = (const float*)d_in[9];
    const float* Wo  = (const float*)d_in[10];
    const float* bo  = (const float*)d_in[11];
    float* out = (float*)d_out;

    float *q, *k, *v, *ao;
    cudaGetSymbolAddress((void**)&q,  g_q);
    cudaGetSymbolAddress((void**)&k,  g_k);
    cudaGetSymbolAddress((void**)&v,  g_v);
    cudaGetSymbolAddress((void**)&ao, g_ao);

    const size_t attn_smem = ATTN_SMEM_FLOATS * sizeof(float);
    cudaFuncSetAttribute(attn_kernel, cudaFuncAttributeMaxDynamicSharedMemorySize,
                         (int)attn_smem);

    dim3 gqkv(DM / 128, TTOK / 64, 3);   // (4, 49, 3)
    gemm_qkv_kernel<<<gqkv, 128>>>(xq, xk, pos, Wq, bq, Wk, bk, Wv, bv, q, k, v);

    // 52 q-blocks = sum ceil(ch_i*196/64) for channels [2,4,6,4] (fixed input)
    attn_kernel<<<dim3(52, 8), 128, attn_smem>>>(q, k, v, ch, ao);

    dim3 gg(DM / 128, TTOK / 64);        // (4, 49)
    gemm512_kernel<<<gg, 128>>>(ao, nullptr, Wo, bo, out);
}